// round 1
// baseline (speedup 1.0000x reference)
#include <cuda_runtime.h>
#include <cuda_bf16.h>

#define GN 50000
#define GE 800000
#define IND 128
#define OUTD 64
#define ALPHA 0.2f

// ---- scratch (device globals: no allocations allowed) ----
__device__ float  g_h[GN * OUTD];        // 12.8 MB
__device__ float  g_asrc[GN];
__device__ float  g_adst[GN];
__device__ int    g_deg[GN];
__device__ int    g_off[GN + 1];
__device__ int    g_cnt[GN];
__device__ float2 g_ed[GE];              // (dst-as-bits, exp(e)) pairs, CSR order by src
__device__ float  g_sum[1];

// ---------------------------------------------------------------------------
// 0) zero counters
__global__ void k_zero() {
    int i = blockIdx.x * blockDim.x + threadIdx.x;
    if (i < GN) { g_deg[i] = 0; g_cnt[i] = 0; }
    if (i == 0) g_sum[0] = 0.0f;
}

// ---------------------------------------------------------------------------
// 1) h = x @ W    (32 nodes per block, W + x tile staged in smem)
__global__ __launch_bounds__(256) void k_gemm(const float* __restrict__ x,
                                              const float* __restrict__ W) {
    __shared__ float Ws[IND * OUTD];   // 32 KB
    __shared__ float xs[32 * IND];     // 16 KB
    const int t = threadIdx.x;

    // load W [128,64] row-major
    for (int i = t; i < IND * OUTD / 4; i += 256)
        ((float4*)Ws)[i] = ((const float4*)W)[i];

    const int node0 = blockIdx.x * 32;
    // load x tile [32,128]
    for (int i = t; i < 32 * IND / 4; i += 256) {
        int nl = i / (IND / 4);
        int n = node0 + nl;
        ((float4*)xs)[i] = (n < GN) ? ((const float4*)x)[(long)n * (IND / 4) + (i % (IND / 4))]
                                    : make_float4(0.f, 0.f, 0.f, 0.f);
    }
    __syncthreads();

    const int nl = t >> 3;       // node within tile (0..31)
    const int cg = t & 7;        // col group (8 cols each)
    float acc[8];
#pragma unroll
    for (int c = 0; c < 8; c++) acc[c] = 0.f;

    const float4* xs4 = (const float4*)(xs + nl * IND);
#pragma unroll 4
    for (int k4 = 0; k4 < IND / 4; k4++) {
        float4 xv = xs4[k4];
        float xa[4] = {xv.x, xv.y, xv.z, xv.w};
#pragma unroll
        for (int kk = 0; kk < 4; kk++) {
            const float* wrow = Ws + (k4 * 4 + kk) * OUTD + cg * 8;
            float4 w0 = ((const float4*)wrow)[0];
            float4 w1 = ((const float4*)wrow)[1];
            float xk = xa[kk];
            acc[0] += xk * w0.x; acc[1] += xk * w0.y;
            acc[2] += xk * w0.z; acc[3] += xk * w0.w;
            acc[4] += xk * w1.x; acc[5] += xk * w1.y;
            acc[6] += xk * w1.z; acc[7] += xk * w1.w;
        }
    }
    const int n = node0 + nl;
    if (n < GN) {
        float4* o = (float4*)(g_h + (long)n * OUTD + cg * 8);
        o[0] = make_float4(acc[0], acc[1], acc[2], acc[3]);
        o[1] = make_float4(acc[4], acc[5], acc[6], acc[7]);
    }
}

// ---------------------------------------------------------------------------
// 2) a_src[n] = h[n]·a[:64],  a_dst[n] = h[n]·a[64:]
__global__ void k_att(const float* __restrict__ a) {
    int n = blockIdx.x * blockDim.x + threadIdx.x;
    if (n >= GN) return;
    const float4* h4 = (const float4*)(g_h + (long)n * OUTD);
    float s = 0.f, d = 0.f;
#pragma unroll
    for (int i = 0; i < OUTD / 4; i++) {
        float4 hv = h4[i];
        float4 av = ((const float4*)a)[i];
        float4 bv = ((const float4*)a)[OUTD / 4 + i];
        s += hv.x * av.x + hv.y * av.y + hv.z * av.z + hv.w * av.w;
        d += hv.x * bv.x + hv.y * bv.y + hv.z * bv.z + hv.w * bv.w;
    }
    g_asrc[n] = s;
    g_adst[n] = d;
}

// ---------------------------------------------------------------------------
// 3) per-edge: degree histogram + global sum of exp(leakyrelu(score))
__global__ void k_edge(const int* __restrict__ src, const int* __restrict__ dst) {
    __shared__ float bsum;
    if (threadIdx.x == 0) bsum = 0.f;
    __syncthreads();

    int i = blockIdx.x * blockDim.x + threadIdx.x;
    float w = 0.f;
    if (i < GE) {
        int s = src[i], d = dst[i];
        atomicAdd(&g_deg[s], 1);
        float e = g_asrc[s] + g_adst[d];
        e = (e > 0.f) ? e : ALPHA * e;
        w = expf(e);
    }
#pragma unroll
    for (int o = 16; o > 0; o >>= 1) w += __shfl_down_sync(0xffffffffu, w, o);
    if ((threadIdx.x & 31) == 0) atomicAdd(&bsum, w);
    __syncthreads();
    if (threadIdx.x == 0) atomicAdd(&g_sum[0], bsum);
}

// ---------------------------------------------------------------------------
// 4) exclusive scan of degrees -> CSR offsets (single block, 1024 threads)
__global__ __launch_bounds__(1024) void k_scan() {
    __shared__ int wsum[32];
    const int lane = threadIdx.x & 31, wid = threadIdx.x >> 5;
    int carry = 0;
    for (int base = 0; base < GN; base += 1024) {
        int i = base + threadIdx.x;
        int v = (i < GN) ? g_deg[i] : 0;
        int x = v;
#pragma unroll
        for (int o = 1; o < 32; o <<= 1) {
            int y = __shfl_up_sync(0xffffffffu, x, o);
            if (lane >= o) x += y;
        }
        if (lane == 31) wsum[wid] = x;
        __syncthreads();
        if (wid == 0) {
            int ws = wsum[lane];
#pragma unroll
            for (int o = 1; o < 32; o <<= 1) {
                int y = __shfl_up_sync(0xffffffffu, ws, o);
                if (lane >= o) ws += y;
            }
            wsum[lane] = ws;
        }
        __syncthreads();
        int prefix = (wid > 0) ? wsum[wid - 1] : 0;
        if (i < GN) g_off[i] = carry + prefix + (x - v);  // exclusive
        carry += wsum[31];
        __syncthreads();
    }
    if (threadIdx.x == 0) g_off[GN] = carry;
}

// ---------------------------------------------------------------------------
// 5) scatter edges into CSR slots: (dst, exp_score) pairs grouped by src
__global__ void k_scatter(const int* __restrict__ src, const int* __restrict__ dst) {
    int i = blockIdx.x * blockDim.x + threadIdx.x;
    if (i >= GE) return;
    int s = src[i], d = dst[i];
    float e = g_asrc[s] + g_adst[d];
    e = (e > 0.f) ? e : ALPHA * e;
    float w = expf(e);
    int ofs = atomicAdd(&g_cnt[s], 1);
    int pos = g_off[s] + ofs;
    g_ed[pos] = make_float2(__int_as_float(d), w);
}

// ---------------------------------------------------------------------------
// 6) warp-per-node SpMM + elu.  lane handles cols [2*lane, 2*lane+1]
__global__ __launch_bounds__(256) void k_spmm(float* __restrict__ out) {
    const int warp = (blockIdx.x * blockDim.x + threadIdx.x) >> 5;
    const int lane = threadIdx.x & 31;
    if (warp >= GN) return;
    const int start = g_off[warp], end = g_off[warp + 1];
    const float2* __restrict__ h2 = (const float2*)g_h;
    float2 acc = make_float2(0.f, 0.f);
    int j = start;
#pragma unroll 1
    for (; j + 4 <= end; j += 4) {
        float2 e0 = g_ed[j + 0];
        float2 e1 = g_ed[j + 1];
        float2 e2 = g_ed[j + 2];
        float2 e3 = g_ed[j + 3];
        float2 h0 = h2[(long)__float_as_int(e0.x) * 32 + lane];
        float2 h1 = h2[(long)__float_as_int(e1.x) * 32 + lane];
        float2 h2v = h2[(long)__float_as_int(e2.x) * 32 + lane];
        float2 h3 = h2[(long)__float_as_int(e3.x) * 32 + lane];
        acc.x += e0.y * h0.x;  acc.y += e0.y * h0.y;
        acc.x += e1.y * h1.x;  acc.y += e1.y * h1.y;
        acc.x += e2.y * h2v.x; acc.y += e2.y * h2v.y;
        acc.x += e3.y * h3.x;  acc.y += e3.y * h3.y;
    }
    for (; j < end; j++) {
        float2 ed = g_ed[j];
        float2 hv = h2[(long)__float_as_int(ed.x) * 32 + lane];
        acc.x += ed.y * hv.x;
        acc.y += ed.y * hv.y;
    }
    float inv = 1.0f / g_sum[0];
    float vx = acc.x * inv, vy = acc.y * inv;
    vx = (vx > 0.f) ? vx : expm1f(vx);
    vy = (vy > 0.f) ? vy : expm1f(vy);
    ((float2*)out)[(long)warp * 32 + lane] = make_float2(vx, vy);
}

// ---------------------------------------------------------------------------
extern "C" void kernel_launch(void* const* d_in, const int* in_sizes, int n_in,
                              void* d_out, int out_size) {
    const float* x  = (const float*)d_in[0];   // [50000,128]
    const float* W  = (const float*)d_in[1];   // [128,64]
    const float* a  = (const float*)d_in[2];   // [128,1]
    const int* ei   = (const int*)d_in[3];     // [2,800000]
    const int* src  = ei;
    const int* dst  = ei + GE;
    float* out = (float*)d_out;

    k_zero<<<(GN + 255) / 256, 256>>>();
    k_gemm<<<(GN + 31) / 32, 256>>>(x, W);
    k_att<<<(GN + 255) / 256, 256>>>(a);
    k_edge<<<(GE + 255) / 256, 256>>>(src, dst);
    k_scan<<<1, 1024>>>();
    k_scatter<<<(GE + 255) / 256, 256>>>(src, dst);
    k_spmm<<<(GN * 32 + 255) / 256, 256>>>(out);
}

// round 2
// speedup vs baseline: 2.0976x; 2.0976x over previous
#include <cuda_runtime.h>
#include <cuda_bf16.h>

#define GN 50000
#define GE 800000
#define IND 128
#define OUTD 64
#define ALPHA 0.2f
#define XPITCH 132

// ---- scratch (device globals, zero-initialized at module load) ----
__device__ float  g_h[GN * OUTD];        // 12.8 MB
__device__ float  g_asrc[GN];
__device__ float  g_adst[GN];
__device__ int    g_deg[GN];             // zeroed by k_scan after use (replay-safe)
__device__ int    g_off[GN + 1];
__device__ int    g_off2[GN];            // scatter cursor, rewritten by k_scan
__device__ float2 g_ed[GE];              // (dst-as-bits, exp(e)) CSR by src
__device__ float  g_sum;                 // zeroed by k_scan before k_scatter

// ---------------------------------------------------------------------------
// 1) degree histogram (RED, no return)
__global__ void k_deg(const int* __restrict__ src) {
    int i = blockIdx.x * blockDim.x + threadIdx.x;
    if (i < GE) atomicAdd(&g_deg[src[i]], 1);
}

// ---------------------------------------------------------------------------
// 2) h = x @ W  (64 nodes x 64 cols per block, 128 threads, 8x4 per thread)
//    epilogue also computes a_src = h.a[:64], a_dst = h.a[64:]
__global__ __launch_bounds__(128) void k_gemm(const float* __restrict__ x,
                                              const float* __restrict__ W,
                                              const float* __restrict__ a) {
    __shared__ float Ws[IND * OUTD];        // [k][col], 32 KB
    __shared__ float Xs[64 * XPITCH];       // [node][k], pitch 132, ~33.8 KB
    const int tid = threadIdx.x;
    const int node0 = blockIdx.x * 64;

    // load W [128,64] row-major (same layout)
#pragma unroll
    for (int i = 0; i < 16; i++)
        ((float4*)Ws)[tid + 128 * i] = ((const float4*)W)[tid + 128 * i];

    // load x tile [64,128]; coalesced float4, conflict-free STS.128
#pragma unroll
    for (int it = 0; it < 16; it++) {
        int idx = tid + 128 * it;
        int node = idx >> 5, kq = idx & 31;
        int n = node0 + node;
        float4 v = (n < GN) ? ((const float4*)x)[(long)n * 32 + kq]
                            : make_float4(0.f, 0.f, 0.f, 0.f);
        *(float4*)(Xs + node * XPITCH + kq * 4) = v;
    }
    __syncthreads();

    const int cg = tid & 15;   // cols 4cg..4cg+3
    const int ng = tid >> 4;   // nodes ng + 8j, j=0..7 (strided: conflict-free LDS)
    float4 acc[8];
#pragma unroll
    for (int j = 0; j < 8; j++) acc[j] = make_float4(0.f, 0.f, 0.f, 0.f);

    const float* wp = Ws + cg * 4;
#pragma unroll 2
    for (int k = 0; k < IND; k += 4) {
        float4 w0 = *(const float4*)(wp + (k + 0) * OUTD);
        float4 w1 = *(const float4*)(wp + (k + 1) * OUTD);
        float4 w2 = *(const float4*)(wp + (k + 2) * OUTD);
        float4 w3 = *(const float4*)(wp + (k + 3) * OUTD);
#pragma unroll
        for (int j = 0; j < 8; j++) {
            float4 xv = *(const float4*)(Xs + (ng + 8 * j) * XPITCH + k);
            acc[j].x += xv.x * w0.x; acc[j].y += xv.x * w0.y;
            acc[j].z += xv.x * w0.z; acc[j].w += xv.x * w0.w;
            acc[j].x += xv.y * w1.x; acc[j].y += xv.y * w1.y;
            acc[j].z += xv.y * w1.z; acc[j].w += xv.y * w1.w;
            acc[j].x += xv.z * w2.x; acc[j].y += xv.z * w2.y;
            acc[j].z += xv.z * w2.z; acc[j].w += xv.z * w2.w;
            acc[j].x += xv.w * w3.x; acc[j].y += xv.w * w3.y;
            acc[j].z += xv.w * w3.z; acc[j].w += xv.w * w3.w;
        }
    }

    // epilogue: att score partials + reduction over the 16 col-group lanes
    float a0x = a[4 * cg + 0], a0y = a[4 * cg + 1], a0z = a[4 * cg + 2], a0w = a[4 * cg + 3];
    float a1x = a[64 + 4 * cg + 0], a1y = a[64 + 4 * cg + 1],
          a1z = a[64 + 4 * cg + 2], a1w = a[64 + 4 * cg + 3];
    float s[8], d[8];
#pragma unroll
    for (int j = 0; j < 8; j++) {
        s[j] = acc[j].x * a0x + acc[j].y * a0y + acc[j].z * a0z + acc[j].w * a0w;
        d[j] = acc[j].x * a1x + acc[j].y * a1y + acc[j].z * a1z + acc[j].w * a1w;
    }
#pragma unroll
    for (int o = 1; o < 16; o <<= 1) {
#pragma unroll
        for (int j = 0; j < 8; j++) {
            s[j] += __shfl_xor_sync(0xffffffffu, s[j], o);
            d[j] += __shfl_xor_sync(0xffffffffu, d[j], o);
        }
    }

#pragma unroll
    for (int j = 0; j < 8; j++) {
        int n = node0 + ng + 8 * j;
        if (n < GN)
            *(float4*)(g_h + (long)n * OUTD + 4 * cg) = acc[j];
    }
    if (cg == 0) {
#pragma unroll
        for (int j = 0; j < 8; j++) {
            int n = node0 + ng + 8 * j;
            if (n < GN) { g_asrc[n] = s[j]; g_adst[n] = d[j]; }
        }
    }
}

// ---------------------------------------------------------------------------
// 3) exclusive scan of degrees -> g_off / g_off2; zero g_deg and g_sum
__global__ __launch_bounds__(1024) void k_scan() {
    __shared__ int wsum[32];
    const int lane = threadIdx.x & 31, wid = threadIdx.x >> 5;
    const int NQ = GN / 4;                 // 12500
    int carry = 0;
    for (int base = 0; base < NQ; base += 1024) {
        int i4 = base + threadIdx.x;
        int4 v = (i4 < NQ) ? ((const int4*)g_deg)[i4] : make_int4(0, 0, 0, 0);
        int t = v.x + v.y + v.z + v.w;
        int xinc = t;
#pragma unroll
        for (int o = 1; o < 32; o <<= 1) {
            int y = __shfl_up_sync(0xffffffffu, xinc, o);
            if (lane >= o) xinc += y;
        }
        if (lane == 31) wsum[wid] = xinc;
        __syncthreads();
        if (wid == 0) {
            int ws = wsum[lane];
#pragma unroll
            for (int o = 1; o < 32; o <<= 1) {
                int y = __shfl_up_sync(0xffffffffu, ws, o);
                if (lane >= o) ws += y;
            }
            wsum[lane] = ws;
        }
        __syncthreads();
        int pre = carry + (wid ? wsum[wid - 1] : 0) + (xinc - t);
        if (i4 < NQ) {
            int4 o4;
            o4.x = pre;
            o4.y = pre + v.x;
            o4.z = o4.y + v.y;
            o4.w = o4.z + v.z;
            ((int4*)g_off)[i4]  = o4;
            ((int4*)g_off2)[i4] = o4;
            ((int4*)g_deg)[i4]  = make_int4(0, 0, 0, 0);   // reset for next replay
        }
        carry += wsum[31];
        __syncthreads();
    }
    if (threadIdx.x == 0) { g_off[GN] = carry; g_sum = 0.f; }
}

// ---------------------------------------------------------------------------
// 4) fused edge pass: score + exp + scatter into CSR + global sum
__global__ void k_scatter(const int* __restrict__ src, const int* __restrict__ dst) {
    __shared__ float bsum;
    if (threadIdx.x == 0) bsum = 0.f;
    __syncthreads();
    int i = blockIdx.x * blockDim.x + threadIdx.x;
    float w = 0.f;
    if (i < GE) {
        int sN = src[i], dN = dst[i];
        float e = g_asrc[sN] + g_adst[dN];
        e = (e > 0.f) ? e : ALPHA * e;
        w = __expf(e);
        int pos = atomicAdd(&g_off2[sN], 1);
        g_ed[pos] = make_float2(__int_as_float(dN), w);
    }
#pragma unroll
    for (int o = 16; o > 0; o >>= 1) w += __shfl_down_sync(0xffffffffu, w, o);
    if ((threadIdx.x & 31) == 0) atomicAdd(&bsum, w);
    __syncthreads();
    if (threadIdx.x == 0) atomicAdd(&g_sum, bsum);
}

// ---------------------------------------------------------------------------
// 5) warp-per-node SpMM + softmax normalize + elu
__global__ __launch_bounds__(256) void k_spmm(float* __restrict__ out) {
    const int warp = (blockIdx.x * blockDim.x + threadIdx.x) >> 5;
    const int lane = threadIdx.x & 31;
    if (warp >= GN) return;
    const int start = g_off[warp], end = g_off[warp + 1];
    const float2* __restrict__ h2 = (const float2*)g_h;
    float2 acc = make_float2(0.f, 0.f);
    int j = start;
#pragma unroll 1
    for (; j + 4 <= end; j += 4) {
        float2 e0 = g_ed[j + 0];
        float2 e1 = g_ed[j + 1];
        float2 e2 = g_ed[j + 2];
        float2 e3 = g_ed[j + 3];
        float2 h0 = h2[(long)__float_as_int(e0.x) * 32 + lane];
        float2 h1 = h2[(long)__float_as_int(e1.x) * 32 + lane];
        float2 hv2 = h2[(long)__float_as_int(e2.x) * 32 + lane];
        float2 h3 = h2[(long)__float_as_int(e3.x) * 32 + lane];
        acc.x += e0.y * h0.x;  acc.y += e0.y * h0.y;
        acc.x += e1.y * h1.x;  acc.y += e1.y * h1.y;
        acc.x += e2.y * hv2.x; acc.y += e2.y * hv2.y;
        acc.x += e3.y * h3.x;  acc.y += e3.y * h3.y;
    }
    for (; j < end; j++) {
        float2 ed = g_ed[j];
        float2 hv = h2[(long)__float_as_int(ed.x) * 32 + lane];
        acc.x += ed.y * hv.x;
        acc.y += ed.y * hv.y;
    }
    float inv = 1.0f / g_sum;
    float vx = acc.x * inv, vy = acc.y * inv;
    vx = (vx > 0.f) ? vx : expm1f(vx);
    vy = (vy > 0.f) ? vy : expm1f(vy);
    ((float2*)out)[(long)warp * 32 + lane] = make_float2(vx, vy);
}

// ---------------------------------------------------------------------------
extern "C" void kernel_launch(void* const* d_in, const int* in_sizes, int n_in,
                              void* d_out, int out_size) {
    const float* x  = (const float*)d_in[0];   // [50000,128]
    const float* W  = (const float*)d_in[1];   // [128,64]
    const float* a  = (const float*)d_in[2];   // [128,1]
    const int* ei   = (const int*)d_in[3];     // [2,800000]
    const int* src  = ei;
    const int* dst  = ei + GE;
    float* out = (float*)d_out;

    k_deg    <<<(GE + 255) / 256, 256>>>(src);
    k_gemm   <<<(GN + 63) / 64, 128>>>(x, W, a);
    k_scan   <<<1, 1024>>>();
    k_scatter<<<(GE + 255) / 256, 256>>>(src, dst);
    k_spmm   <<<(GN * 32 + 255) / 256, 256>>>(out);
}